// round 9
// baseline (speedup 1.0000x reference)
#include <cuda_runtime.h>
#include <cstdint>

#define HRR   1024
#define NDEC  16
#define OUTW  (HRR * (2 + 2 * NDEC))   // 34816 floats per row
#define ZPAD  34                       // zbuf row stride in float2 (17 float4, 272B)
#define MAXB  8192

typedef unsigned long long ull;        // packed complex: lo=re, hi=im

// Precomputed decoder spectra (packed): g_G[d*HRR+k] = conj(FFT(dec_d))[k]/1024
__device__ ull g_G[NDEC * HRR];
// Forward spectra scratch: g_Z[row*HRR + k] = FFT(p + i*l)[k]
__device__ ull g_Z[(size_t)MAXB * HRR];

// ---------------- packed f32x2 primitives ----------------
static __device__ __forceinline__ ull pk(float x, float y) {
    ull r;
    asm("mov.b64 %0, {%1, %2};" : "=l"(r)
        : "r"(__float_as_uint(x)), "r"(__float_as_uint(y)));
    return r;
}
static __device__ __forceinline__ float2 unpk(ull a) {
    unsigned x, y;
    asm("mov.b64 {%0, %1}, %2;" : "=r"(x), "=r"(y) : "l"(a));
    return make_float2(__uint_as_float(x), __uint_as_float(y));
}
static __device__ __forceinline__ ull pswap(ull a) {   // {im, re}
    unsigned x, y;
    asm("mov.b64 {%0, %1}, %2;" : "=r"(x), "=r"(y) : "l"(a));
    ull r;
    asm("mov.b64 %0, {%1, %2};" : "=l"(r) : "r"(y), "r"(x));
    return r;
}
static __device__ __forceinline__ ull padd(ull a, ull b) {
    ull d; asm("add.rn.f32x2 %0, %1, %2;" : "=l"(d) : "l"(a), "l"(b)); return d;
}
static __device__ __forceinline__ ull pmul(ull a, ull b) {
    ull d; asm("mul.rn.f32x2 %0, %1, %2;" : "=l"(d) : "l"(a), "l"(b)); return d;
}
static __device__ __forceinline__ ull pfma(ull a, ull b, ull c) {
    ull d; asm("fma.rn.f32x2 %0, %1, %2, %3;" : "=l"(d) : "l"(a), "l"(b), "l"(c)); return d;
}
// a - b  (exact: fma with -1 multiplier)
static __device__ __forceinline__ ull psub(ull a, ull b, ull neg1) {
    return pfma(b, neg1, a);
}
// packed complex multiply by twiddle given wxx={wx,wx}, wmy={-wy,wy}
static __device__ __forceinline__ ull pcmulw(ull d, ull wxx, ull wmy) {
    return pfma(pswap(d), wmy, pmul(d, wxx));
}

static __device__ __forceinline__ float2 cmul(float2 a, float2 b) {
    return make_float2(fmaf(a.x, b.x, -a.y * b.y), fmaf(a.x, b.y, a.y * b.x));
}

// cos/sin(2*pi*t/32), t = 0..15
__device__ constexpr float C32T[16] = {
    1.0f,          0.980785280f,  0.923879533f,  0.831469612f,
    0.707106781f,  0.555570233f,  0.382683432f,  0.195090322f,
    0.0f,         -0.195090322f, -0.382683432f, -0.555570233f,
   -0.707106781f, -0.831469612f, -0.923879533f, -0.980785280f };
__device__ constexpr float S32T[16] = {
    0.0f,          0.195090322f,  0.382683432f,  0.555570233f,
    0.707106781f,  0.831469612f,  0.923879533f,  0.980785280f,
    1.0f,          0.980785280f,  0.923879533f,  0.831469612f,
    0.707106781f,  0.555570233f,  0.382683432f,  0.195090322f };

__device__ __host__ constexpr int brev5(int x) {
    return ((x & 1) << 4) | ((x & 2) << 2) | (x & 4) | ((x & 8) >> 2) | ((x & 16) >> 4);
}

// Swizzle for the 32x32 float2 transpose buffer: conflict-free in both the
// store (fixed c, lane varies) and load (fixed b, lane varies) directions.
static __device__ __forceinline__ int swz(int r, int c) { return r * 32 + ((c + r) & 31); }

// One DIF radix-2 stage of an in-register 32-point FFT, packed f32x2 math.
// SGN = -1: forward (e^{-2pi i}); SGN = +1: inverse kernel (no 1/N).
template<int SGN, int M>
static __device__ __forceinline__ void fft32_stage(ull v[32], ull neg1) {
    constexpr int H = M / 2;
    constexpr int TS = 32 / M;
#pragma unroll
    for (int g = 0; g < 32; g += M) {
#pragma unroll
        for (int j = 0; j < H; j++) {
            const int t = j * TS;           // twiddle exponent, 0..15
            ull a = v[g + j], b = v[g + j + H];
            v[g + j] = padd(a, b);
            ull d = psub(a, b, neg1);
            if (t == 0) {
                v[g + j + H] = d;
            } else if (t == 8) {            // multiply by (0, SGN): swap + sign
                float2 s = unpk(d);
                v[g + j + H] = (SGN < 0) ? pk(s.y, -s.x) : pk(-s.y, s.x);
            } else {
                const float wc = C32T[t];
                const float ws = (SGN < 0) ? -S32T[t] : S32T[t];
                v[g + j + H] = pcmulw(d, pk(wc, wc), pk(-ws, ws));
            }
        }
    }
}

template<int SGN>
static __device__ __forceinline__ void fft32(ull v[32]) {
    const ull neg1 = pk(-1.0f, -1.0f);
    fft32_stage<SGN, 32>(v, neg1);
    fft32_stage<SGN, 16>(v, neg1);
    fft32_stage<SGN, 8>(v, neg1);
    fft32_stage<SGN, 4>(v, neg1);
    fft32_stage<SGN, 2>(v, neg1);
}

// Warp-level 1024-point complex FFT (four-step, 32 lanes x 32 packed regs).
// Input:  v[a] on lane b = x[32*a + b]   (natural order)
// Output: v[r] on lane c = X[c + 32*brev5(r)]
// Twiddles W_1024^{SGN*lane*c} via FOUR independent 7-step chains.
template<int SGN>
static __device__ __forceinline__ void warp_fft1024(ull (&v)[32], int lane, float2* tb) {
    fft32<SGN>(v);   // per-lane FFT over a -> frequency index c (bit-reversed in regs)

    const float ang = (float)SGN * (6.283185307179586f / 1024.0f) * (float)lane;
    float s1, c1, s8, c8, s16, c16;
    __sincosf(ang, &s1, &c1);
    __sincosf(8.0f * ang, &s8, &c8);
    __sincosf(16.0f * ang, &s16, &c16);
    const float2 w = make_float2(c1, s1);
    float2 tA = make_float2(1.0f, 0.0f);
    float2 tB = make_float2(c8, s8);
    float2 tC = make_float2(c16, s16);
    float2 tD = cmul(tB, tC);
#pragma unroll
    for (int c = 0; c < 8; c++) {
        // brev5(c+8) = brev5(c)+2, brev5(c+16) = +1, brev5(c+24) = +3
        tb[swz(lane, c)]      = cmul(unpk(v[brev5(c)]),     tA);
        tb[swz(lane, c + 8)]  = cmul(unpk(v[brev5(c) + 2]), tB);
        tb[swz(lane, c + 16)] = cmul(unpk(v[brev5(c) + 1]), tC);
        tb[swz(lane, c + 24)] = cmul(unpk(v[brev5(c) + 3]), tD);
        tA = cmul(tA, w); tB = cmul(tB, w); tC = cmul(tC, w); tD = cmul(tD, w);
    }
    __syncwarp();
#pragma unroll
    for (int b = 0; b < 32; b++)
        v[b] = *(const ull*)&tb[swz(b, lane)];   // ld.shared.b64, lane holds fixed c
    __syncwarp();   // protect tb before caller's next use

    fft32<SGN>(v);   // FFT over b -> index d (bit-reversed in regs)
}

// ---------------------------------------------------------------------------
// Kernel 1: decoder spectra. One block (1 warp) per decoder.
__global__ __launch_bounds__(32)
void hrr_prep_kernel(const float* __restrict__ dec) {
    __shared__ float2 tb[32 * 32];
    const int lane = threadIdx.x;
    const int d = blockIdx.x;
    ull v[32];
#pragma unroll
    for (int a = 0; a < 32; a++)
        v[a] = pk(__ldg(&dec[d * HRR + 32 * a + lane]), 0.0f);
    warp_fft1024<-1>(v, lane, tb);
    const float inv = 1.0f / 1024.0f;
#pragma unroll
    for (int r = 0; r < 32; r++) {
        int k = lane + 32 * brev5(r);
        float2 s = unpk(v[r]);
        g_G[d * HRR + k] = pk(s.x * inv, -s.y * inv);   // conj / N
    }
}

// ---------------------------------------------------------------------------
// Kernel A: forward FFTs, one WARP per row (balanced: every warp identical).
// Also performs the p/l passthrough copy into out[0:2048) for its row.
__global__ __launch_bounds__(128)
void hrr_fwd_kernel(const float* __restrict__ P,
                    const float* __restrict__ L,
                    float* __restrict__ out, int B) {
    __shared__ float2 tb[4][32 * 32];
    const int wid  = threadIdx.x >> 5;
    const int lane = threadIdx.x & 31;
    const int row  = blockIdx.x * 4 + wid;
    if (row >= B) return;

    const float* pr = P + (size_t)row * HRR;
    const float* lr = L + (size_t)row * HRR;
    float* outr = out + (size_t)row * OUTW;

    // Passthrough copy (brings p/l lines into L1 for the element loads below)
    const float4* p4 = (const float4*)pr;
    const float4* l4 = (const float4*)lr;
    float4* o4 = (float4*)outr;
#pragma unroll
    for (int i = 0; i < 8; i++) {
        __stcs(&o4[lane + 32 * i],       __ldg(&p4[lane + 32 * i]));
        __stcs(&o4[256 + lane + 32 * i], __ldg(&l4[lane + 32 * i]));
    }

    ull v[32];
#pragma unroll
    for (int a = 0; a < 32; a++)
        v[a] = pk(__ldg(&pr[32 * a + lane]), __ldg(&lr[32 * a + lane]));
    warp_fft1024<-1>(v, lane, tb[wid]);

    // Store spectrum in natural k order (coalesced per instruction; plain
    // write-back stores so Z has a chance to stay L2-resident for kernel B)
    ull* Zr = g_Z + (size_t)row * HRR;
#pragma unroll
    for (int r = 0; r < 32; r++)
        Zr[lane + 32 * brev5(r)] = v[r];
}

// ---------------------------------------------------------------------------
// Kernel B: one CTA (4 warps) per row, 4 inverse FFTs per warp. Balanced.
__global__ __launch_bounds__(128)
void hrr_inv_kernel(float* __restrict__ out) {
    // Z spectrum, lane-transposed: zbuf[lane*ZPAD + a] = Z[32a + lane].
    __shared__ alignas(16) float2 zbuf[32 * ZPAD];
    __shared__ float2 tb[4][32 * 32];

    const int b    = blockIdx.x;
    const int tid  = threadIdx.x;
    const int wid  = tid >> 5;
    const int lane = tid & 31;

    float* outr = out + (size_t)b * OUTW;
    const ull* Zr = g_Z + (size_t)b * HRR;

    // Fill zbuf from global Z: k = tid + 128j  ->  zbuf[lane][4j + wid]
#pragma unroll
    for (int j = 0; j < 8; j++) {
        ull zv = Zr[tid + 128 * j];                       // coalesced LDG.64
        *(ull*)&zbuf[lane * ZPAD + 4 * j + wid] = zv;
    }
    __syncthreads();

    ull v[32];
    const float4* z4 = (const float4*)(zbuf + lane * ZPAD);
#pragma unroll 1
    for (int d = wid; d < NDEC; d += 4) {
        const ull* G = g_G + d * HRR;
#pragma unroll
        for (int j = 0; j < 16; j++) {
            float4 zz = z4[j];                                  // a = 2j, 2j+1
            float2 g0 = unpk(__ldg(&G[32 * (2 * j)     + lane]));
            float2 g1 = unpk(__ldg(&G[32 * (2 * j + 1) + lane]));
            float2 r0 = cmul(make_float2(zz.x, zz.y), g0);
            float2 r1 = cmul(make_float2(zz.z, zz.w), g1);
            v[2 * j]     = pk(r0.x, r0.y);
            v[2 * j + 1] = pk(r1.x, r1.y);
        }
        warp_fft1024<1>(v, lane, tb[wid]);

        float* op = outr + 2 * HRR + d * HRR;                // assoc_p block
        float* ol = outr + 2 * HRR + NDEC * HRR + d * HRR;   // assoc_l block
#pragma unroll
        for (int r = 0; r < 32; r++) {
            int k = lane + 32 * brev5(r);
            float2 s = unpk(v[r]);
            __stcs(&op[k], s.x);
            __stcs(&ol[k], s.y);
        }
    }
}

// ---------------------------------------------------------------------------
extern "C" void kernel_launch(void* const* d_in, const int* in_sizes, int n_in,
                              void* d_out, int out_size) {
    // metadata order: problemhrr [B,1024], lemmahrr [B,1024], decoders [16,1024]
    const float* P = (const float*)d_in[0];
    const float* L = (const float*)d_in[1];
    const float* D = (const float*)d_in[2];
    // defensive: identify the decoders tensor by its unique size
    if (in_sizes[0] == NDEC * HRR) {
        D = (const float*)d_in[0]; P = (const float*)d_in[1]; L = (const float*)d_in[2];
    } else if (in_sizes[1] == NDEC * HRR) {
        P = (const float*)d_in[0]; D = (const float*)d_in[1]; L = (const float*)d_in[2];
    }
    int B = out_size / OUTW;
    if (B > MAXB) B = MAXB;

    hrr_prep_kernel<<<NDEC, 32>>>(D);
    hrr_fwd_kernel<<<(B + 3) / 4, 128>>>(P, L, (float*)d_out, B);
    hrr_inv_kernel<<<B, 128>>>((float*)d_out);
}